// round 2
// baseline (speedup 1.0000x reference)
#include <cuda_runtime.h>
#include <cstddef>

#define TT   512
#define NB   4096
#define BC   32          // batch elements per CTA
#define NTH  256
#define HS   36          // padded row stride (floats) for h/x tiles: 16B-aligned, low STS conflicts

struct SmemT {
    float4 whh0[64 * 64];   // [k][u] -> gates (i,f,g,o) of unit u, weight vs h0[k]
    float4 wih1[64 * 64];   // [k][u] -> weight vs h0_new[k]
    float4 whh1[64 * 64];   // [k][u] -> weight vs h1[k]
    float4 wih0[6 * 64];    // [j][u] -> weight vs x[j]
    float4 b0[64];          // summed biases layer 0, gate-interleaved
    float4 b1[64];
    float  h0[64 * HS];     // [k][b]
    float  h1[64 * HS];
    float  xs[2][6 * HS];   // double-buffered x_t staging [j][b]
};

__device__ __forceinline__ float sigm(float x) {
    float e = __expf(-x);
    return __fdividef(1.0f, 1.0f + e);
}
__device__ __forceinline__ float tanh_f(float x) {
    return fmaf(2.0f, sigm(2.0f * x), -1.0f);
}

__device__ __forceinline__ void mac8(float* a, float h, float4 wA, float4 wB) {
    a[0] = fmaf(h, wA.x, a[0]); a[1] = fmaf(h, wA.y, a[1]);
    a[2] = fmaf(h, wA.z, a[2]); a[3] = fmaf(h, wA.w, a[3]);
    a[4] = fmaf(h, wB.x, a[4]); a[5] = fmaf(h, wB.y, a[5]);
    a[6] = fmaf(h, wB.z, a[6]); a[7] = fmaf(h, wB.w, a[7]);
}
__device__ __forceinline__ void mac32(float* acc, float4 hv, float4 wA, float4 wB) {
    mac8(acc +  0, hv.x, wA, wB);
    mac8(acc +  8, hv.y, wA, wB);
    mac8(acc + 16, hv.z, wA, wB);
    mac8(acc + 24, hv.w, wA, wB);
}

__global__ void __launch_bounds__(NTH, 1) lstm2_kernel(
    const float* __restrict__ x,
    const float* __restrict__ Wih0, const float* __restrict__ Whh0,
    const float* __restrict__ bih0, const float* __restrict__ bhh0,
    const float* __restrict__ Wih1, const float* __restrict__ Whh1,
    const float* __restrict__ bih1, const float* __restrict__ bhh1,
    const float* __restrict__ Wfc,  const float* __restrict__ bfc,
    float* __restrict__ out)
{
    extern __shared__ char smraw[];
    SmemT* s = reinterpret_cast<SmemT*>(smraw);
    const int tid    = threadIdx.x;
    const int batch0 = blockIdx.x * BC;

    // ---- one-time weight staging: gate-interleave so each unit's (i,f,g,o) is a float4 ----
    for (int idx = tid; idx < 64 * 64; idx += NTH) {
        int k = idx >> 6, u = idx & 63;
        s->whh0[idx] = make_float4(Whh0[u * 64 + k], Whh0[(64 + u) * 64 + k],
                                   Whh0[(128 + u) * 64 + k], Whh0[(192 + u) * 64 + k]);
        s->wih1[idx] = make_float4(Wih1[u * 64 + k], Wih1[(64 + u) * 64 + k],
                                   Wih1[(128 + u) * 64 + k], Wih1[(192 + u) * 64 + k]);
        s->whh1[idx] = make_float4(Whh1[u * 64 + k], Whh1[(64 + u) * 64 + k],
                                   Whh1[(128 + u) * 64 + k], Whh1[(192 + u) * 64 + k]);
    }
    for (int idx = tid; idx < 6 * 64; idx += NTH) {
        int j = idx >> 6, u = idx & 63;
        s->wih0[idx] = make_float4(Wih0[u * 6 + j], Wih0[(64 + u) * 6 + j],
                                   Wih0[(128 + u) * 6 + j], Wih0[(192 + u) * 6 + j]);
    }
    if (tid < 64) {
        int u = tid;
        s->b0[u] = make_float4(bih0[u] + bhh0[u],             bih0[64 + u] + bhh0[64 + u],
                               bih0[128 + u] + bhh0[128 + u], bih0[192 + u] + bhh0[192 + u]);
        s->b1[u] = make_float4(bih1[u] + bhh1[u],             bih1[64 + u] + bhh1[64 + u],
                               bih1[128 + u] + bhh1[128 + u], bih1[192 + u] + bhh1[192 + u]);
    }
    for (int idx = tid; idx < 64 * HS; idx += NTH) { s->h0[idx] = 0.f; s->h1[idx] = 0.f; }
    if (tid < BC * 6) {
        int b = tid / 6, j = tid % 6;
        s->xs[0][j * HS + b] = x[(size_t)(batch0 + b) * (TT * 6) + j];
    }
    __syncthreads();

    const int ug = tid & 31;   // owns units ug and ug+32
    const int bg = tid >> 5;   // owns batch bg*4 .. bg*4+3
    const int bb = bg * 4;

    float c0[8], c1[8];        // cell states, [bi*2 + ui]
#pragma unroll
    for (int i = 0; i < 8; i++) { c0[i] = 0.f; c1[i] = 0.f; }

    for (int t = 0; t < TT; t++) {
        const int cur = t & 1;

        // prefetch x(t+1) into registers (hidden behind layer-0 GEMM)
        float xv = 0.f;
        if (tid < BC * 6 && t + 1 < TT) {
            int b = tid / 6, j = tid % 6;
            xv = x[(size_t)(batch0 + b) * (TT * 6) + (size_t)(t + 1) * 6 + j];
        }

        // ================= layer 0: gates = b0 + Wih0 x_t + Whh0 h0 =================
        float acc[32];
        {
            float4 bA = s->b0[ug], bB = s->b0[ug + 32];
#pragma unroll
            for (int bi = 0; bi < 4; bi++) {
                acc[bi * 8 + 0] = bA.x; acc[bi * 8 + 1] = bA.y; acc[bi * 8 + 2] = bA.z; acc[bi * 8 + 3] = bA.w;
                acc[bi * 8 + 4] = bB.x; acc[bi * 8 + 5] = bB.y; acc[bi * 8 + 6] = bB.z; acc[bi * 8 + 7] = bB.w;
            }
        }
#pragma unroll
        for (int j = 0; j < 6; j++) {
            float4 hv = *(const float4*)&s->xs[cur][j * HS + bb];
            float4 wA = s->wih0[j * 64 + ug];
            float4 wB = s->wih0[j * 64 + 32 + ug];
            mac32(acc, hv, wA, wB);
        }
#pragma unroll 4
        for (int k = 0; k < 64; k++) {
            float4 hv = *(const float4*)&s->h0[k * HS + bb];
            float4 wA = s->whh0[k * 64 + ug];
            float4 wB = s->whh0[k * 64 + 32 + ug];
            mac32(acc, hv, wA, wB);
        }
        __syncthreads();   // everyone done reading old h0 / xs[cur]

        // ---- epilogue 0: cell update in registers, publish new h0 ----
#pragma unroll
        for (int bi = 0; bi < 4; bi++) {
#pragma unroll
            for (int ui = 0; ui < 2; ui++) {
                float* a = &acc[bi * 8 + ui * 4];
                float ig = sigm(a[0]);
                float fg = sigm(a[1]);
                float gg = tanh_f(a[2]);
                float og = sigm(a[3]);
                float c  = fmaf(fg, c0[bi * 2 + ui], ig * gg);
                c0[bi * 2 + ui] = c;
                s->h0[(ug + ui * 32) * HS + bb + bi] = og * tanh_f(c);
            }
        }
        if (tid < BC * 6 && t + 1 < TT) {
            int b = tid / 6, j = tid % 6;
            s->xs[cur ^ 1][j * HS + b] = xv;
        }
        __syncthreads();   // new h0 (and next x) visible

        // ================= layer 1: gates = b1 + Wih1 h0_new + Whh1 h1 =================
        {
            float4 bA = s->b1[ug], bB = s->b1[ug + 32];
#pragma unroll
            for (int bi = 0; bi < 4; bi++) {
                acc[bi * 8 + 0] = bA.x; acc[bi * 8 + 1] = bA.y; acc[bi * 8 + 2] = bA.z; acc[bi * 8 + 3] = bA.w;
                acc[bi * 8 + 4] = bB.x; acc[bi * 8 + 5] = bB.y; acc[bi * 8 + 6] = bB.z; acc[bi * 8 + 7] = bB.w;
            }
        }
#pragma unroll 4
        for (int k = 0; k < 64; k++) {
            float4 hv = *(const float4*)&s->h0[k * HS + bb];
            float4 wA = s->wih1[k * 64 + ug];
            float4 wB = s->wih1[k * 64 + 32 + ug];
            mac32(acc, hv, wA, wB);
        }
#pragma unroll 4
        for (int k = 0; k < 64; k++) {
            float4 hv = *(const float4*)&s->h1[k * HS + bb];
            float4 wA = s->whh1[k * 64 + ug];
            float4 wB = s->whh1[k * 64 + 32 + ug];
            mac32(acc, hv, wA, wB);
        }
        __syncthreads();   // everyone done reading old h1 (and h0)

        // ---- epilogue 1 ----
#pragma unroll
        for (int bi = 0; bi < 4; bi++) {
#pragma unroll
            for (int ui = 0; ui < 2; ui++) {
                float* a = &acc[bi * 8 + ui * 4];
                float ig = sigm(a[0]);
                float fg = sigm(a[1]);
                float gg = tanh_f(a[2]);
                float og = sigm(a[3]);
                float c  = fmaf(fg, c1[bi * 2 + ui], ig * gg);
                c1[bi * 2 + ui] = c;
                s->h1[(ug + ui * 32) * HS + bb + bi] = og * tanh_f(c);
            }
        }
        // no trailing sync needed: next iteration's barriers order all remaining hazards
    }
    __syncthreads();

    // ---- final FC: out[b] = h1_T @ Wfc^T + bfc ----
    if (tid < BC * 3) {
        int b = tid / 3, oc = tid - b * 3;
        float sum = bfc[oc];
#pragma unroll
        for (int u = 0; u < 64; u++)
            sum = fmaf(s->h1[u * HS + b], Wfc[oc * 64 + u], sum);
        out[(size_t)(batch0 + b) * 3 + oc] = sum;
    }
}

extern "C" void kernel_launch(void* const* d_in, const int* in_sizes, int n_in,
                              void* d_out, int out_size)
{
    (void)in_sizes; (void)n_in; (void)out_size;
    cudaFuncSetAttribute(lstm2_kernel, cudaFuncAttributeMaxDynamicSharedMemorySize,
                         (int)sizeof(SmemT));
    lstm2_kernel<<<NB / BC, NTH, sizeof(SmemT)>>>(
        (const float*)d_in[0],
        (const float*)d_in[1], (const float*)d_in[2],
        (const float*)d_in[3], (const float*)d_in[4],
        (const float*)d_in[5], (const float*)d_in[6],
        (const float*)d_in[7], (const float*)d_in[8],
        (const float*)d_in[9], (const float*)d_in[10],
        (float*)d_out);
}

// round 4
// speedup vs baseline: 1.0021x; 1.0021x over previous
#include <cuda_runtime.h>
#include <cstddef>

#define TT   512
#define NB   4096
#define BC   32          // batch elements per CTA
#define NTH  256
#define HS   36          // padded row stride (floats) for h/x tiles: 16B-aligned, low STS conflicts

struct SmemT {
    float4 whh0[64 * 64];   // [k][u] -> gates (i,f,g,o) of unit u, weight vs h0[k]
    float4 wih1[64 * 64];   // [k][u] -> weight vs h0_new[k]
    float4 whh1[64 * 64];   // [k][u] -> weight vs h1[k]
    float4 wih0[6 * 64];    // [j][u] -> weight vs x[j]
    float4 b0[64];          // summed biases layer 0, gate-interleaved
    float4 b1[64];
    float  h0[64 * HS];     // [k][b]
    float  h1[64 * HS];
    float  xs[2][6 * HS];   // double-buffered x_t staging [j][b]
};

__device__ __forceinline__ float sigm(float x) {
    float e = __expf(-x);
    return __fdividef(1.0f, 1.0f + e);
}
__device__ __forceinline__ float tanh_f(float x) {
    return fmaf(2.0f, sigm(2.0f * x), -1.0f);
}

__device__ __forceinline__ void mac8(float* a, float h, float4 wA, float4 wB) {
    a[0] = fmaf(h, wA.x, a[0]); a[1] = fmaf(h, wA.y, a[1]);
    a[2] = fmaf(h, wA.z, a[2]); a[3] = fmaf(h, wA.w, a[3]);
    a[4] = fmaf(h, wB.x, a[4]); a[5] = fmaf(h, wB.y, a[5]);
    a[6] = fmaf(h, wB.z, a[6]); a[7] = fmaf(h, wB.w, a[7]);
}
__device__ __forceinline__ void mac32(float* acc, float4 hv, float4 wA, float4 wB) {
    mac8(acc +  0, hv.x, wA, wB);
    mac8(acc +  8, hv.y, wA, wB);
    mac8(acc + 16, hv.z, wA, wB);
    mac8(acc + 24, hv.w, wA, wB);
}

__global__ void __launch_bounds__(NTH, 1) lstm2_kernel(
    const float* __restrict__ x,
    const float* __restrict__ Wih0, const float* __restrict__ Whh0,
    const float* __restrict__ bih0, const float* __restrict__ bhh0,
    const float* __restrict__ Wih1, const float* __restrict__ Whh1,
    const float* __restrict__ bih1, const float* __restrict__ bhh1,
    const float* __restrict__ Wfc,  const float* __restrict__ bfc,
    float* __restrict__ out)
{
    extern __shared__ char smraw[];
    SmemT* s = reinterpret_cast<SmemT*>(smraw);
    const int tid    = threadIdx.x;
    const int batch0 = blockIdx.x * BC;

    // ---- one-time weight staging: gate-interleave so each unit's (i,f,g,o) is a float4 ----
    for (int idx = tid; idx < 64 * 64; idx += NTH) {
        int k = idx >> 6, u = idx & 63;
        s->whh0[idx] = make_float4(Whh0[u * 64 + k], Whh0[(64 + u) * 64 + k],
                                   Whh0[(128 + u) * 64 + k], Whh0[(192 + u) * 64 + k]);
        s->wih1[idx] = make_float4(Wih1[u * 64 + k], Wih1[(64 + u) * 64 + k],
                                   Wih1[(128 + u) * 64 + k], Wih1[(192 + u) * 64 + k]);
        s->whh1[idx] = make_float4(Whh1[u * 64 + k], Whh1[(64 + u) * 64 + k],
                                   Whh1[(128 + u) * 64 + k], Whh1[(192 + u) * 64 + k]);
    }
    for (int idx = tid; idx < 6 * 64; idx += NTH) {
        int j = idx >> 6, u = idx & 63;
        s->wih0[idx] = make_float4(Wih0[u * 6 + j], Wih0[(64 + u) * 6 + j],
                                   Wih0[(128 + u) * 6 + j], Wih0[(192 + u) * 6 + j]);
    }
    if (tid < 64) {
        int u = tid;
        s->b0[u] = make_float4(bih0[u] + bhh0[u],             bih0[64 + u] + bhh0[64 + u],
                               bih0[128 + u] + bhh0[128 + u], bih0[192 + u] + bhh0[192 + u]);
        s->b1[u] = make_float4(bih1[u] + bhh1[u],             bih1[64 + u] + bhh1[64 + u],
                               bih1[128 + u] + bhh1[128 + u], bih1[192 + u] + bhh1[192 + u]);
    }
    for (int idx = tid; idx < 64 * HS; idx += NTH) { s->h0[idx] = 0.f; s->h1[idx] = 0.f; }
    if (tid < BC * 6) {
        int b = tid / 6, j = tid % 6;
        s->xs[0][j * HS + b] = x[(size_t)(batch0 + b) * (TT * 6) + j];
    }
    __syncthreads();

    const int ug = tid & 31;   // owns units ug and ug+32
    const int bg = tid >> 5;   // owns batch bg*4 .. bg*4+3
    const int bb = bg * 4;

    float c0[8], c1[8];        // cell states, [bi*2 + ui]
#pragma unroll
    for (int i = 0; i < 8; i++) { c0[i] = 0.f; c1[i] = 0.f; }

    for (int t = 0; t < TT; t++) {
        const int cur = t & 1;

        // prefetch x(t+1) into registers (hidden behind layer-0 GEMM)
        float xv = 0.f;
        if (tid < BC * 6 && t + 1 < TT) {
            int b = tid / 6, j = tid % 6;
            xv = x[(size_t)(batch0 + b) * (TT * 6) + (size_t)(t + 1) * 6 + j];
        }

        // ================= layer 0: gates = b0 + Wih0 x_t + Whh0 h0 =================
        float acc[32];
        {
            float4 bA = s->b0[ug], bB = s->b0[ug + 32];
#pragma unroll
            for (int bi = 0; bi < 4; bi++) {
                acc[bi * 8 + 0] = bA.x; acc[bi * 8 + 1] = bA.y; acc[bi * 8 + 2] = bA.z; acc[bi * 8 + 3] = bA.w;
                acc[bi * 8 + 4] = bB.x; acc[bi * 8 + 5] = bB.y; acc[bi * 8 + 6] = bB.z; acc[bi * 8 + 7] = bB.w;
            }
        }
#pragma unroll
        for (int j = 0; j < 6; j++) {
            float4 hv = *(const float4*)&s->xs[cur][j * HS + bb];
            float4 wA = s->wih0[j * 64 + ug];
            float4 wB = s->wih0[j * 64 + 32 + ug];
            mac32(acc, hv, wA, wB);
        }
#pragma unroll 4
        for (int k = 0; k < 64; k++) {
            float4 hv = *(const float4*)&s->h0[k * HS + bb];
            float4 wA = s->whh0[k * 64 + ug];
            float4 wB = s->whh0[k * 64 + 32 + ug];
            mac32(acc, hv, wA, wB);
        }
        __syncthreads();   // everyone done reading old h0 / xs[cur]

        // ---- epilogue 0: cell update in registers, publish new h0 ----
#pragma unroll
        for (int bi = 0; bi < 4; bi++) {
#pragma unroll
            for (int ui = 0; ui < 2; ui++) {
                float* a = &acc[bi * 8 + ui * 4];
                float ig = sigm(a[0]);
                float fg = sigm(a[1]);
                float gg = tanh_f(a[2]);
                float og = sigm(a[3]);
                float c  = fmaf(fg, c0[bi * 2 + ui], ig * gg);
                c0[bi * 2 + ui] = c;
                s->h0[(ug + ui * 32) * HS + bb + bi] = og * tanh_f(c);
            }
        }
        if (tid < BC * 6 && t + 1 < TT) {
            int b = tid / 6, j = tid % 6;
            s->xs[cur ^ 1][j * HS + b] = xv;
        }
        __syncthreads();   // new h0 (and next x) visible

        // ================= layer 1: gates = b1 + Wih1 h0_new + Whh1 h1 =================
        {
            float4 bA = s->b1[ug], bB = s->b1[ug + 32];
#pragma unroll
            for (int bi = 0; bi < 4; bi++) {
                acc[bi * 8 + 0] = bA.x; acc[bi * 8 + 1] = bA.y; acc[bi * 8 + 2] = bA.z; acc[bi * 8 + 3] = bA.w;
                acc[bi * 8 + 4] = bB.x; acc[bi * 8 + 5] = bB.y; acc[bi * 8 + 6] = bB.z; acc[bi * 8 + 7] = bB.w;
            }
        }
#pragma unroll 4
        for (int k = 0; k < 64; k++) {
            float4 hv = *(const float4*)&s->h0[k * HS + bb];
            float4 wA = s->wih1[k * 64 + ug];
            float4 wB = s->wih1[k * 64 + 32 + ug];
            mac32(acc, hv, wA, wB);
        }
#pragma unroll 4
        for (int k = 0; k < 64; k++) {
            float4 hv = *(const float4*)&s->h1[k * HS + bb];
            float4 wA = s->whh1[k * 64 + ug];
            float4 wB = s->whh1[k * 64 + 32 + ug];
            mac32(acc, hv, wA, wB);
        }
        __syncthreads();   // everyone done reading old h1 (and h0)

        // ---- epilogue 1 ----
#pragma unroll
        for (int bi = 0; bi < 4; bi++) {
#pragma unroll
            for (int ui = 0; ui < 2; ui++) {
                float* a = &acc[bi * 8 + ui * 4];
                float ig = sigm(a[0]);
                float fg = sigm(a[1]);
                float gg = tanh_f(a[2]);
                float og = sigm(a[3]);
                float c  = fmaf(fg, c1[bi * 2 + ui], ig * gg);
                c1[bi * 2 + ui] = c;
                s->h1[(ug + ui * 32) * HS + bb + bi] = og * tanh_f(c);
            }
        }
        // no trailing sync needed: next iteration's barriers order all remaining hazards
    }
    __syncthreads();

    // ---- final FC: out[b] = h1_T @ Wfc^T + bfc ----
    if (tid < BC * 3) {
        int b = tid / 3, oc = tid - b * 3;
        float sum = bfc[oc];
#pragma unroll
        for (int u = 0; u < 64; u++)
            sum = fmaf(s->h1[u * HS + b], Wfc[oc * 64 + u], sum);
        out[(size_t)(batch0 + b) * 3 + oc] = sum;
    }
}

extern "C" void kernel_launch(void* const* d_in, const int* in_sizes, int n_in,
                              void* d_out, int out_size)
{
    (void)in_sizes; (void)n_in; (void)out_size;
    cudaFuncSetAttribute(lstm2_kernel, cudaFuncAttributeMaxDynamicSharedMemorySize,
                         (int)sizeof(SmemT));
    lstm2_kernel<<<NB / BC, NTH, sizeof(SmemT)>>>(
        (const float*)d_in[0],
        (const float*)d_in[1], (const float*)d_in[2],
        (const float*)d_in[3], (const float*)d_in[4],
        (const float*)d_in[5], (const float*)d_in[6],
        (const float*)d_in[7], (const float*)d_in[8],
        (const float*)d_in[9], (const float*)d_in[10],
        (float*)d_out);
}